// round 2
// baseline (speedup 1.0000x reference)
#include <cuda_runtime.h>
#include <cstdint>

// IIR TPT-SVF via chunked scan with 128-sample warm-up (pole radius ~0.911,
// truncation ~6.6e-6 << 1e-3). R2: double occupancy (CHUNK_L=128 -> 1024
// blocks) + cp.async double-buffered staging so tile t+1 loads overlap
// compute of tile t.

#define BATCH   64
#define NSAMP   131072
#define CHUNK_L 128
#define WARM    128
#define TILE    64
#define NCHUNKS (NSAMP / CHUNK_L)            // 1024
#define NTILES  ((CHUNK_L + WARM) / TILE)    // 4
#define WARM_TILES (WARM / TILE)             // 2
#define SMSTRIDE 66                          // even (8B align), 2-way LDS conflict only

__device__ __forceinline__ uint32_t smem_u32(const void* p) {
    return (uint32_t)__cvta_generic_to_shared(p);
}

__global__ __launch_bounds__(BATCH) void svf_kernel(
    const float* __restrict__ audio,
    const float* __restrict__ gp,
    const float* __restrict__ twoRp,
    const float* __restrict__ mixp,
    float* __restrict__ out)
{
    __shared__ float sm[2][BATCH * SMSTRIDE];   // 2 * 16896 B = 33792 B

    const int tid   = threadIdx.x;
    const int lane  = tid & 31;
    const int half  = tid >> 5;                 // staging row group: half*32 .. +31
    const int chunk = blockIdx.x;
    const int base  = chunk * CHUNK_L - WARM;

    // ---- fold filter constants ----
    const float g    = *gp;
    const float twoR = *twoRp;
    const float m0 = mixp[0], m1 = mixp[1], m2 = mixp[2];

    const float T   = 1.0f / (1.0f + g * (g + twoR));
    const float h00 = T;
    const float h01 = -g * T;
    const float h10 = g * T;
    const float h11 = (twoR * g + 1.0f) * T;
    const float gb0 = g * T;
    const float gb1 = g * g * T;

    const float a00 = 2.0f * h00 - 1.0f;
    const float a01 = 2.0f * h01;
    const float a10 = 2.0f * h10;
    const float a11 = 2.0f * h11 - 1.0f;
    const float bb0 = 2.0f * gb0;
    const float bb1 = 2.0f * gb1;

    const float c0 = twoR * (m0 - m2);
    const float c1 = m1 - m2;
    const float cx = m2;
    const float e0 = c0 * h00 + c1 * h10;
    const float e1 = c0 * h01 + c1 * h11;
    const float ex = c0 * gb0 + c1 * gb1 + cx;

    // ---- staging lambda: tile index -> buffer (cp.async, 8B granules) ----
    // thread (half, lane) stages rows [half*32, half*32+32) at columns (2*lane, 2*lane+1)
    auto stage = [&](int t, int buf) {
        const int pos0 = base + t * TILE;
        float* dst0 = &sm[buf][(half * 32) * SMSTRIDE + 2 * lane];
        if (pos0 >= 0) {
            const float* src0 = audio + (size_t)(half * 32) * NSAMP + pos0 + 2 * lane;
            uint32_t sp = smem_u32(dst0);
            #pragma unroll
            for (int i = 0; i < 32; ++i) {
                asm volatile("cp.async.ca.shared.global [%0], [%1], 8;\n"
                             :: "r"(sp + (uint32_t)(i * SMSTRIDE * 4)),
                                "l"(src0 + (size_t)i * NSAMP));
            }
        } else {
            #pragma unroll
            for (int i = 0; i < 32; ++i)
                *(float2*)(dst0 + i * SMSTRIDE) = make_float2(0.0f, 0.0f);
        }
        asm volatile("cp.async.commit_group;\n");
    };

    float s0 = 0.0f, s1 = 0.0f;

    stage(0, 0);                                // preload tile 0

    for (int t = 0; t < NTILES; ++t) {
        const int buf  = t & 1;
        const int pos0 = base + t * TILE;

        if (t + 1 < NTILES) {
            stage(t + 1, buf ^ 1);              // kick next tile, then wait for this one
            asm volatile("cp.async.wait_group 1;\n");
        } else {
            asm volatile("cp.async.wait_group 0;\n");
        }
        __syncthreads();

        // ---- serial recurrence over this tile, in place (x -> out) ----
        float* row = &sm[buf][tid * SMSTRIDE];
        #pragma unroll 8
        for (int j = 0; j < TILE; ++j) {
            const float x  = row[j];
            const float o  = fmaf(e0, s0, fmaf(e1, s1, ex * x));
            const float n0 = fmaf(a00, s0, fmaf(a01, s1, bb0 * x));
            const float n1 = fmaf(a10, s0, fmaf(a11, s1, bb1 * x));
            s0 = n0;
            s1 = n1;
            row[j] = o;
        }
        __syncthreads();

        // ---- stage out (float2, coalesced) for non-warm-up tiles ----
        if (t >= WARM_TILES) {
            const float* src0 = &sm[buf][(half * 32) * SMSTRIDE + 2 * lane];
            float* dst0 = out + (size_t)(half * 32) * NSAMP + pos0 + 2 * lane;
            #pragma unroll
            for (int i = 0; i < 32; ++i)
                *(float2*)(dst0 + (size_t)i * NSAMP) = *(const float2*)(src0 + i * SMSTRIDE);
        }
        __syncthreads();                        // protect buf before it is refilled
    }
}

extern "C" void kernel_launch(void* const* d_in, const int* in_sizes, int n_in,
                              void* d_out, int out_size) {
    const float* audio = (const float*)d_in[0];
    const float* g     = (const float*)d_in[1];
    const float* twoR  = (const float*)d_in[2];
    const float* mix   = (const float*)d_in[3];
    float* out         = (float*)d_out;

    svf_kernel<<<NCHUNKS, BATCH>>>(audio, g, twoR, mix, out);
}

// round 3
// speedup vs baseline: 2.2311x; 2.2311x over previous
#include <cuda_runtime.h>
#include <cstdint>

// TPT-SVF IIR via chunked scan, 128-sample warm-up (pole radius ~0.911 ->
// truncation ~7e-6 << 1e-3).
// R3: warp-autonomous blocks (32 thr), cp.async.cg 16B double-buffered tiles,
// XOR-swizzled float4 smem, recurrence unrolled x4 (A^4 form) for ILP.

#define BATCH   64
#define NSAMP   131072
#define CHUNK_L 128
#define WARM    128
#define TILE    64
#define NCHUNKS (NSAMP / CHUNK_L)            // 1024
#define NTILES  ((CHUNK_L + WARM) / TILE)    // 4
#define WARM_TILES (WARM / TILE)             // 2

// swizzled float4 index inside one 32-row x 16-chunk tile
#define SWZ(row, c) (((row) << 4) + ((c) ^ ((row) & 15)))

__device__ __forceinline__ uint32_t smem_u32(const void* p) {
    return (uint32_t)__cvta_generic_to_shared(p);
}

__global__ __launch_bounds__(32) void svf_kernel(
    const float* __restrict__ audio,
    const float* __restrict__ gp,
    const float* __restrict__ twoRp,
    const float* __restrict__ mixp,
    float* __restrict__ out)
{
    __shared__ float4 sm[2][32 * 16];        // 2 x 8KB tiles

    const int lane   = threadIdx.x;
    const int chunk  = blockIdx.x >> 1;
    const int rbase  = (blockIdx.x & 1) * 32;      // batch-row base for this warp
    const int base   = chunk * CHUNK_L - WARM;

    // ---------------- fold filter constants ----------------
    const float g    = *gp;
    const float twoR = *twoRp;
    const float m0 = mixp[0], m1 = mixp[1], m2 = mixp[2];

    const float T   = 1.0f / (1.0f + g * (g + twoR));
    const float h00 = T,            h01 = -g * T;
    const float h10 = g * T,        h11 = (twoR * g + 1.0f) * T;
    const float gb0 = g * T,        gb1 = g * g * T;

    // one-step transition A = 2H - I, input gain b = 2*gHB
    const float a00 = 2.0f * h00 - 1.0f, a01 = 2.0f * h01;
    const float a10 = 2.0f * h10,        a11 = 2.0f * h11 - 1.0f;
    const float b0  = 2.0f * gb0,        b1  = 2.0f * gb1;

    // output row vector: out_t = e.s_t + ex*x_t
    const float c0 = twoR * (m0 - m2);
    const float c1 = m1 - m2;
    const float cx = m2;
    const float e0 = c0 * h00 + c1 * h10;
    const float e1 = c0 * h01 + c1 * h11;
    const float ex = c0 * gb0 + c1 * gb1 + cx;

    // powers for 4x unroll
    const float ea0  = e0 * a00 + e1 * a10,  ea1  = e0 * a01 + e1 * a11;   // e*A
    const float ea20 = ea0 * a00 + ea1 * a10, ea21 = ea0 * a01 + ea1 * a11; // e*A^2
    const float ea30 = ea20 * a00 + ea21 * a10, ea31 = ea20 * a01 + ea21 * a11; // e*A^3

    const float eb   = e0 * b0 + e1 * b1;
    const float eab  = ea0 * b0 + ea1 * b1;
    const float ea2b = ea20 * b0 + ea21 * b1;

    const float ab0  = a00 * b0 + a01 * b1,  ab1  = a10 * b0 + a11 * b1;   // A*b
    const float a2b0 = a00 * ab0 + a01 * ab1, a2b1 = a10 * ab0 + a11 * ab1; // A^2*b
    const float a3b0 = a00 * a2b0 + a01 * a2b1, a3b1 = a10 * a2b0 + a11 * a2b1; // A^3*b

    // A^2 then A^4
    const float p00 = a00 * a00 + a01 * a10, p01 = a00 * a01 + a01 * a11;
    const float p10 = a10 * a00 + a11 * a10, p11 = a10 * a01 + a11 * a11;
    const float q00 = p00 * p00 + p01 * p10, q01 = p00 * p01 + p01 * p11;
    const float q10 = p10 * p00 + p11 * p10, q11 = p10 * p01 + p11 * p11;

    // ---------------- staging: one tile -> smem via cp.async 16B ----------------
    auto stage = [&](int t, int buf) {
        const int pos0 = base + t * TILE;
        if (pos0 >= 0) {
            #pragma unroll
            for (int k = 0; k < 16; ++k) {
                const int f   = lane + 32 * k;       // 0..511
                const int row = f >> 4;              // 0..31
                const int c   = f & 15;              // float4 chunk in time
                const float* src = audio + (size_t)(rbase + row) * NSAMP + pos0 + 4 * c;
                uint32_t dst = smem_u32(&sm[buf][SWZ(row, c)]);
                asm volatile("cp.async.cg.shared.global [%0], [%1], 16;\n"
                             :: "r"(dst), "l"(src));
            }
        }
        asm volatile("cp.async.commit_group;\n");    // keep group counting uniform
    };

    float s0 = 0.0f, s1 = 0.0f;

    stage(0, 0);

    for (int t = 0; t < NTILES; ++t) {
        const int buf  = t & 1;
        const int pos0 = base + t * TILE;

        if (t + 1 < NTILES) {
            stage(t + 1, buf ^ 1);
            asm volatile("cp.async.wait_group 1;\n");
        } else {
            asm volatile("cp.async.wait_group 0;\n");
        }
        __syncwarp();

        if (t < WARM_TILES) {
            // ---- warm-up: state update only ----
            if (pos0 >= 0) {
                #pragma unroll 4
                for (int c = 0; c < 16; ++c) {
                    const float4 x = sm[buf][SWZ(lane, c)];
                    const float n0 = fmaf(q00, s0, fmaf(q01, s1,
                                     fmaf(a3b0, x.x, fmaf(a2b0, x.y,
                                     fmaf(ab0, x.z, b0 * x.w)))));
                    const float n1 = fmaf(q10, s0, fmaf(q11, s1,
                                     fmaf(a3b1, x.x, fmaf(a2b1, x.y,
                                     fmaf(ab1, x.z, b1 * x.w)))));
                    s0 = n0; s1 = n1;
                }
            }
        } else {
            // ---- real region: outputs + state, in place ----
            #pragma unroll 4
            for (int c = 0; c < 16; ++c) {
                const float4 x = sm[buf][SWZ(lane, c)];
                float4 o;
                o.x = fmaf(e0, s0, fmaf(e1, s1, ex * x.x));
                o.y = fmaf(ea0, s0, fmaf(ea1, s1,
                      fmaf(eb, x.x, ex * x.y)));
                o.z = fmaf(ea20, s0, fmaf(ea21, s1,
                      fmaf(eab, x.x, fmaf(eb, x.y, ex * x.z))));
                o.w = fmaf(ea30, s0, fmaf(ea31, s1,
                      fmaf(ea2b, x.x, fmaf(eab, x.y, fmaf(eb, x.z, ex * x.w)))));
                const float n0 = fmaf(q00, s0, fmaf(q01, s1,
                                 fmaf(a3b0, x.x, fmaf(a2b0, x.y,
                                 fmaf(ab0, x.z, b0 * x.w)))));
                const float n1 = fmaf(q10, s0, fmaf(q11, s1,
                                 fmaf(a3b1, x.x, fmaf(a2b1, x.y,
                                 fmaf(ab1, x.z, b1 * x.w)))));
                s0 = n0; s1 = n1;
                sm[buf][SWZ(lane, c)] = o;
            }
            __syncwarp();

            // ---- stage out: coalesced float4 stores ----
            #pragma unroll
            for (int k = 0; k < 16; ++k) {
                const int f   = lane + 32 * k;
                const int row = f >> 4;
                const int c   = f & 15;
                const float4 v = sm[buf][SWZ(row, c)];
                *(float4*)(out + (size_t)(rbase + row) * NSAMP + pos0 + 4 * c) = v;
            }
        }
        __syncwarp();   // protect buf before it is refilled next iteration
    }
}

extern "C" void kernel_launch(void* const* d_in, const int* in_sizes, int n_in,
                              void* d_out, int out_size) {
    const float* audio = (const float*)d_in[0];
    const float* g     = (const float*)d_in[1];
    const float* twoR  = (const float*)d_in[2];
    const float* mix   = (const float*)d_in[3];
    float* outp        = (float*)d_out;

    // prefer max shared carveout so 14 blocks/SM fit
    static bool carveout_set = false;
    if (!carveout_set) {
        cudaFuncSetAttribute(svf_kernel, cudaFuncAttributePreferredSharedMemoryCarveout,
                             cudaSharedmemCarveoutMaxShared);
        carveout_set = true;
    }

    svf_kernel<<<NCHUNKS * 2, 32>>>(audio, g, twoR, mix, outp);
}

// round 4
// speedup vs baseline: 2.3163x; 1.0382x over previous
#include <cuda_runtime.h>
#include <cstdint>

// TPT-SVF IIR via chunked scan, 128-sample warm-up (pole radius ~0.911 ->
// truncation ~7e-6 << 1e-3).
// R4: CHUNK_L=64 -> 4096 warp-blocks (~28/SM) to fix the grid-limited
// occupancy seen in R3 (occ=16.9%, issue=37%). TILE=32 (8KB smem/block),
// launch_bounds(32,20) to keep regs <= ~102. Warm tiles are state-only.

#define BATCH   64
#define NSAMP   131072
#define CHUNK_L 64
#define WARM    128
#define TILE    32
#define NCHUNKS (NSAMP / CHUNK_L)            // 2048
#define NTILES  ((CHUNK_L + WARM) / TILE)    // 6
#define WARM_TILES (WARM / TILE)             // 4

// swizzled float4 index inside one 32-row x 8-chunk tile (conflict-free LDS.128)
#define SWZ(row, c) (((row) << 3) + ((c) ^ ((row) & 7)))

__device__ __forceinline__ uint32_t smem_u32(const void* p) {
    return (uint32_t)__cvta_generic_to_shared(p);
}

__global__ __launch_bounds__(32, 20) void svf_kernel(
    const float* __restrict__ audio,
    const float* __restrict__ gp,
    const float* __restrict__ twoRp,
    const float* __restrict__ mixp,
    float* __restrict__ out)
{
    __shared__ float4 sm[2][32 * 8];          // 2 x 4KB tiles

    const int lane   = threadIdx.x;
    const int chunk  = blockIdx.x >> 1;
    const int rbase  = (blockIdx.x & 1) * 32;      // batch-row base for this warp
    const int base   = chunk * CHUNK_L - WARM;

    // ---------------- fold filter constants ----------------
    const float g    = *gp;
    const float twoR = *twoRp;
    const float m0 = mixp[0], m1 = mixp[1], m2 = mixp[2];

    const float T   = 1.0f / (1.0f + g * (g + twoR));
    const float h00 = T,            h01 = -g * T;
    const float h10 = g * T,        h11 = (twoR * g + 1.0f) * T;
    const float gb0 = g * T,        gb1 = g * g * T;

    // one-step transition A = 2H - I, input gain b = 2*gHB
    const float a00 = 2.0f * h00 - 1.0f, a01 = 2.0f * h01;
    const float a10 = 2.0f * h10,        a11 = 2.0f * h11 - 1.0f;
    const float b0  = 2.0f * gb0,        b1  = 2.0f * gb1;

    // output row vector: out_t = e.s_t + ex*x_t
    const float c0 = twoR * (m0 - m2);
    const float c1 = m1 - m2;
    const float cx = m2;
    const float e0 = c0 * h00 + c1 * h10;
    const float e1 = c0 * h01 + c1 * h11;
    const float ex = c0 * gb0 + c1 * gb1 + cx;

    // powers for 4x unroll
    const float ea0  = e0 * a00 + e1 * a10,   ea1  = e0 * a01 + e1 * a11;     // e*A
    const float ea20 = ea0 * a00 + ea1 * a10, ea21 = ea0 * a01 + ea1 * a11;   // e*A^2
    const float ea30 = ea20 * a00 + ea21 * a10, ea31 = ea20 * a01 + ea21 * a11; // e*A^3

    const float eb   = e0 * b0 + e1 * b1;
    const float eab  = ea0 * b0 + ea1 * b1;
    const float ea2b = ea20 * b0 + ea21 * b1;

    const float ab0  = a00 * b0 + a01 * b1,   ab1  = a10 * b0 + a11 * b1;     // A*b
    const float a2b0 = a00 * ab0 + a01 * ab1, a2b1 = a10 * ab0 + a11 * ab1;   // A^2*b
    const float a3b0 = a00 * a2b0 + a01 * a2b1, a3b1 = a10 * a2b0 + a11 * a2b1; // A^3*b

    // A^2 then A^4
    const float p00 = a00 * a00 + a01 * a10, p01 = a00 * a01 + a01 * a11;
    const float p10 = a10 * a00 + a11 * a10, p11 = a10 * a01 + a11 * a11;
    const float q00 = p00 * p00 + p01 * p10, q01 = p00 * p01 + p01 * p11;
    const float q10 = p10 * p00 + p11 * p10, q11 = p10 * p01 + p11 * p11;

    // ---------------- staging: one tile -> smem via cp.async 16B ----------------
    // lane stages 8 float4; consecutive lanes cover 128B runs of one row.
    auto stage = [&](int t, int buf) {
        const int pos0 = base + t * TILE;
        if (pos0 >= 0) {
            #pragma unroll
            for (int k = 0; k < 8; ++k) {
                const int f   = lane + 32 * k;       // 0..255
                const int row = f >> 3;              // 0..31
                const int c   = f & 7;               // float4 chunk in time
                const float* src = audio + (size_t)(rbase + row) * NSAMP + pos0 + 4 * c;
                uint32_t dst = smem_u32(&sm[buf][SWZ(row, c)]);
                asm volatile("cp.async.cg.shared.global [%0], [%1], 16;\n"
                             :: "r"(dst), "l"(src));
            }
        }
        asm volatile("cp.async.commit_group;\n");    // uniform group counting
    };

    float s0 = 0.0f, s1 = 0.0f;

    stage(0, 0);

    for (int t = 0; t < NTILES; ++t) {
        const int buf  = t & 1;
        const int pos0 = base + t * TILE;

        if (t + 1 < NTILES) {
            stage(t + 1, buf ^ 1);
            asm volatile("cp.async.wait_group 1;\n");
        } else {
            asm volatile("cp.async.wait_group 0;\n");
        }
        __syncwarp();

        if (t < WARM_TILES) {
            // ---- warm-up: state update only ----
            if (pos0 >= 0) {
                #pragma unroll
                for (int c = 0; c < 8; ++c) {
                    const float4 x = sm[buf][SWZ(lane, c)];
                    const float n0 = fmaf(q00, s0, fmaf(q01, s1,
                                     fmaf(a3b0, x.x, fmaf(a2b0, x.y,
                                     fmaf(ab0, x.z, b0 * x.w)))));
                    const float n1 = fmaf(q10, s0, fmaf(q11, s1,
                                     fmaf(a3b1, x.x, fmaf(a2b1, x.y,
                                     fmaf(ab1, x.z, b1 * x.w)))));
                    s0 = n0; s1 = n1;
                }
            }
        } else {
            // ---- real region: outputs + state, in place ----
            #pragma unroll
            for (int c = 0; c < 8; ++c) {
                const float4 x = sm[buf][SWZ(lane, c)];
                float4 o;
                o.x = fmaf(e0, s0, fmaf(e1, s1, ex * x.x));
                o.y = fmaf(ea0, s0, fmaf(ea1, s1,
                      fmaf(eb, x.x, ex * x.y)));
                o.z = fmaf(ea20, s0, fmaf(ea21, s1,
                      fmaf(eab, x.x, fmaf(eb, x.y, ex * x.z))));
                o.w = fmaf(ea30, s0, fmaf(ea31, s1,
                      fmaf(ea2b, x.x, fmaf(eab, x.y, fmaf(eb, x.z, ex * x.w)))));
                const float n0 = fmaf(q00, s0, fmaf(q01, s1,
                                 fmaf(a3b0, x.x, fmaf(a2b0, x.y,
                                 fmaf(ab0, x.z, b0 * x.w)))));
                const float n1 = fmaf(q10, s0, fmaf(q11, s1,
                                 fmaf(a3b1, x.x, fmaf(a2b1, x.y,
                                 fmaf(ab1, x.z, b1 * x.w)))));
                s0 = n0; s1 = n1;
                sm[buf][SWZ(lane, c)] = o;
            }
            __syncwarp();

            // ---- stage out: coalesced float4 stores ----
            #pragma unroll
            for (int k = 0; k < 8; ++k) {
                const int f   = lane + 32 * k;
                const int row = f >> 3;
                const int c   = f & 7;
                const float4 v = sm[buf][SWZ(row, c)];
                *(float4*)(out + (size_t)(rbase + row) * NSAMP + pos0 + 4 * c) = v;
            }
        }
        __syncwarp();   // protect buf before refill next iteration
    }
}

extern "C" void kernel_launch(void* const* d_in, const int* in_sizes, int n_in,
                              void* d_out, int out_size) {
    const float* audio = (const float*)d_in[0];
    const float* g     = (const float*)d_in[1];
    const float* twoR  = (const float*)d_in[2];
    const float* mix   = (const float*)d_in[3];
    float* outp        = (float*)d_out;

    static bool carveout_set = false;
    if (!carveout_set) {
        cudaFuncSetAttribute(svf_kernel, cudaFuncAttributePreferredSharedMemoryCarveout,
                             cudaSharedmemCarveoutMaxShared);
        carveout_set = true;
    }

    svf_kernel<<<NCHUNKS * 2, 32>>>(audio, g, twoR, mix, outp);
}